// round 3
// baseline (speedup 1.0000x reference)
#include <cuda_runtime.h>
#include <cstdint>

#define DD    2048
#define NBLK  16
#define BATCH 32

// Scratch (no allocations allowed -> __device__ globals; fully rewritten every launch)
__device__ float g_gates[BATCH * NBLK];
__device__ int   g_cnt[NBLK];
__device__ int   g_idx[NBLK * 32];
__device__ float g_gval[NBLK * 32];

// ---------------------------------------------------------------------------
// Kernel 1: gate logits -> sigmoid -> zero 8 smallest; also fill out with bias
// One CTA per batch sample.
// ---------------------------------------------------------------------------
__global__ __launch_bounds__(256) void gate_kernel(
    const float* __restrict__ x, const float* __restrict__ gw,
    const float* __restrict__ gb, const float* __restrict__ bias,
    float* __restrict__ out)
{
    const int b   = blockIdx.x;
    const int tid = threadIdx.x;
    const float* xrow = x + (size_t)b * DD;

    // bias fill (inactive (b,i) outputs are exactly bias[i])
    for (int i = tid; i < DD; i += 256) out[(size_t)b * DD + i] = bias[i];

    float p[NBLK];
#pragma unroll
    for (int j = 0; j < NBLK; j++) p[j] = 0.f;

    for (int k = tid; k < DD; k += 256) {
        const float xv = xrow[k];
        const float4* gr = (const float4*)(gw + (size_t)k * NBLK);
        const float4 w0 = gr[0], w1 = gr[1], w2 = gr[2], w3 = gr[3];
        p[0]  += xv * w0.x;  p[1]  += xv * w0.y;  p[2]  += xv * w0.z;  p[3]  += xv * w0.w;
        p[4]  += xv * w1.x;  p[5]  += xv * w1.y;  p[6]  += xv * w1.z;  p[7]  += xv * w1.w;
        p[8]  += xv * w2.x;  p[9]  += xv * w2.y;  p[10] += xv * w2.z;  p[11] += xv * w2.w;
        p[12] += xv * w3.x;  p[13] += xv * w3.y;  p[14] += xv * w3.z;  p[15] += xv * w3.w;
    }

    __shared__ float red[256 * 17];   // stride 17 -> conflict-free
#pragma unroll
    for (int j = 0; j < NBLK; j++) red[tid * 17 + j] = p[j];
    __syncthreads();
    for (int off = 128; off > 0; off >>= 1) {
        if (tid < off) {
#pragma unroll
            for (int j = 0; j < NBLK; j++)
                red[tid * 17 + j] += red[(tid + off) * 17 + j];
        }
        __syncthreads();
    }

    __shared__ float gv[NBLK];
    if (tid < NBLK) {
        const float t = red[tid] + gb[tid];
        gv[tid] = 1.f / (1.f + expf(-t));
    }
    __syncthreads();

    if (tid == 0) {
        float v[NBLK];
#pragma unroll
        for (int j = 0; j < NBLK; j++) v[j] = gv[j];
        unsigned mask = 0;
        // zero the 8 smallest gates; strict '<' => lowest index wins ties (matches top_k)
        for (int it = 0; it < NBLK / 2; it++) {
            int best = 0; float bv = 3.4e38f;
            for (int j = 0; j < NBLK; j++)
                if (!((mask >> j) & 1u) && v[j] < bv) { bv = v[j]; best = j; }
            mask |= 1u << best;
        }
        for (int j = 0; j < NBLK; j++)
            g_gates[b * NBLK + j] = ((mask >> j) & 1u) ? 0.f : v[j];
    }
}

// ---------------------------------------------------------------------------
// Kernel 2: per-block compaction of active batches (deterministic, tiny)
// ---------------------------------------------------------------------------
__global__ void compact_kernel()
{
    const int nb = threadIdx.x;
    if (nb >= NBLK) return;
    int c = 0;
    for (int b = 0; b < BATCH; b++) {
        const float v = g_gates[b * NBLK + nb];
        if (v != 0.f) { g_idx[nb * 32 + c] = b; g_gval[nb * 32 + c] = v; c++; }
    }
    g_cnt[nb] = c;
    for (int s = c; s < 32; s++) { g_idx[nb * 32 + s] = 0; g_gval[nb * 32 + s] = 0.f; }
}

// ---------------------------------------------------------------------------
// Kernel 3: gated skinny GEMM with f32x2 packed FFMA
// grid = (64 col-tiles of 32 rows, 4 slot-chunks of 8 compacted batches)
// ---------------------------------------------------------------------------
__device__ __forceinline__ unsigned long long ffma2(
    unsigned long long a, unsigned long long b, unsigned long long c)
{
    unsigned long long d;
    asm("fma.rn.f32x2 %0, %1, %2, %3;" : "=l"(d) : "l"(a), "l"(b), "l"(c));
    return d;
}
__device__ __forceinline__ unsigned long long rep2(float w)
{
    unsigned long long d;
    asm("mov.b64 %0, {%1, %1};" : "=l"(d) : "r"(__float_as_uint(w)));
    return d;
}

__global__ __launch_bounds__(256) void main_kernel(
    const float* __restrict__ x, const float* __restrict__ W,
    const float* __restrict__ bias, float* __restrict__ out)
{
    extern __shared__ float smem[];          // 64 KB: xs = float2[4][2048]; later red[32*257]
    float2* xs = (float2*)smem;

    const int c0 = blockIdx.x * 32;          // first output row of this tile
    const int nb = c0 >> 7;                  // gate block (tile stays inside one block)
    const int s0 = blockIdx.y * 8;           // first compacted slot
    const int cnt = g_cnt[nb];
    if (s0 >= cnt) return;                   // idle chunk -> outputs stay = bias

    const int tid = threadIdx.x;

    int   bidx[8];
    float gvl[8];
#pragma unroll
    for (int j = 0; j < 8; j++) {
        bidx[j] = g_idx[nb * 32 + s0 + j];   // padded slots: b=0, gate=0 (store guarded)
        gvl[j]  = g_gval[nb * 32 + s0 + j];
    }

    // stage x as interleaved batch-pairs: xs[p][k] = (x[b2p][k], x[b2p+1][k])
    for (int m = tid; m < 2048; m += 256) {
        const int p = m >> 9;
        const int k = (m & 511) * 4;
        const float4 a = *(const float4*)(x + (size_t)bidx[2 * p]     * DD + k);
        const float4 b = *(const float4*)(x + (size_t)bidx[2 * p + 1] * DD + k);
        float4* dst = (float4*)(xs + p * DD + k);
        dst[0] = make_float4(a.x, b.x, a.y, b.y);
        dst[1] = make_float4(a.z, b.z, a.w, b.w);
    }
    __syncthreads();

    const int cg = tid & 7;                  // 8 column groups x 4 cols
    const int kg = tid >> 3;                 // 32-way K split
    const float* wbase = W + (size_t)(c0 + cg * 4) * DD;

    unsigned long long acc[4][4];            // [pair][col] packed f32x2
#pragma unroll
    for (int p = 0; p < 4; p++)
#pragma unroll
        for (int cc = 0; cc < 4; cc++) acc[p][cc] = 0ull;

    float4 wA[4];
    {
        const int kb = kg * 4;
#pragma unroll
        for (int cc = 0; cc < 4; cc++)
            wA[cc] = *(const float4*)(wbase + (size_t)cc * DD + kb);
    }

#pragma unroll 4
    for (int i = 0; i < 16; i++) {
        const int kb  = i * 128 + kg * 4;
        const int kbn = (kb + 128) & (DD - 1);     // wrap: last prefetch harmless
        float4 wB[4];
#pragma unroll
        for (int cc = 0; cc < 4; cc++)             // prefetch next K-step of weights
            wB[cc] = *(const float4*)(wbase + (size_t)cc * DD + kbn);

        ulonglong2 xv0[4], xv1[4];
#pragma unroll
        for (int p = 0; p < 4; p++) {
            xv0[p] = *(const ulonglong2*)(xs + p * DD + kb);       // k, k+1
            xv1[p] = *(const ulonglong2*)(xs + p * DD + kb + 2);   // k+2, k+3
        }
#pragma unroll
        for (int cc = 0; cc < 4; cc++) {
            const unsigned long long w0 = rep2(wA[cc].x);
            const unsigned long long w1 = rep2(wA[cc].y);
            const unsigned long long w2 = rep2(wA[cc].z);
            const unsigned long long w3 = rep2(wA[cc].w);
#pragma unroll
            for (int p = 0; p < 4; p++) {
                acc[p][cc] = ffma2(xv0[p].x, w0, acc[p][cc]);
                acc[p][cc] = ffma2(xv0[p].y, w1, acc[p][cc]);
                acc[p][cc] = ffma2(xv1[p].x, w2, acc[p][cc]);
                acc[p][cc] = ffma2(xv1[p].y, w3, acc[p][cc]);
            }
        }
#pragma unroll
        for (int cc = 0; cc < 4; cc++) wA[cc] = wB[cc];
    }
    __syncthreads();                         // xs dead; alias as reduction buffer

    // partials: red[kg*257 + slot*32 + col'] -> bank = (kg + cg*4 + cc) % 32, all distinct
    float* red = smem;
#pragma unroll
    for (int p = 0; p < 4; p++) {
#pragma unroll
        for (int cc = 0; cc < 4; cc++) {
            const unsigned long long v = acc[p][cc];
            const float lo = __uint_as_float((unsigned)(v & 0xffffffffu));
            const float hi = __uint_as_float((unsigned)(v >> 32));
            red[kg * 257 + (2 * p)     * 32 + cg * 4 + cc] = lo;
            red[kg * 257 + (2 * p + 1) * 32 + cg * 4 + cc] = hi;
        }
    }
    __syncthreads();

    const int s  = tid >> 5;                 // local slot 0..7
    const int cp = tid & 31;                 // local col 0..31
    float sum = 0.f;
#pragma unroll
    for (int kk = 0; kk < 32; kk++) sum += red[kk * 257 + s * 32 + cp];

    if (s0 + s < cnt)
        out[(size_t)bidx[s] * DD + c0 + cp] = gvl[s] * sum + bias[c0 + cp];
}

// ---------------------------------------------------------------------------
extern "C" void kernel_launch(void* const* d_in, const int* in_sizes, int n_in,
                              void* d_out, int out_size)
{
    (void)in_sizes; (void)n_in; (void)out_size;
    const float* x    = (const float*)d_in[0];
    const float* gw   = (const float*)d_in[1];
    const float* gb   = (const float*)d_in[2];
    const float* W    = (const float*)d_in[3];
    const float* bias = (const float*)d_in[4];
    float* out = (float*)d_out;

    cudaFuncSetAttribute(main_kernel, cudaFuncAttributeMaxDynamicSharedMemorySize, 65536);

    gate_kernel<<<32, 256>>>(x, gw, gb, bias, out);
    compact_kernel<<<1, 32>>>();
    main_kernel<<<dim3(64, 4), 256, 65536>>>(x, W, bias, out);
}

// round 7
// speedup vs baseline: 2.3550x; 2.3550x over previous
#include <cuda_runtime.h>
#include <cstdint>

#define DD    2048
#define NBLK  16
#define BATCH 32

// Scratch (no allocations allowed -> __device__ globals; fully rewritten every launch)
__device__ float g_part[BATCH * 4 * NBLK];   // gate partial sums (per K-slice)
__device__ int   g_cnt[NBLK];
__device__ int   g_idx[NBLK * 32];
__device__ float g_gval[NBLK * 32];

// ---------------------------------------------------------------------------
// Kernel 1: gate partial dot products, K split 4 ways. grid=(32 batches, 4 slices)
// Also fills out with bias (inactive (b,i) outputs are exactly bias[i]).
// ---------------------------------------------------------------------------
__global__ __launch_bounds__(256) void gate_kernel(
    const float* __restrict__ x, const float* __restrict__ gw,
    const float* __restrict__ bias, float* __restrict__ out)
{
    const int b    = blockIdx.x;
    const int ks   = blockIdx.y;
    const int tid  = threadIdx.x;
    const int base = ks * 512;

    // bias fill for this (b, k-slice) range
    out[(size_t)b * DD + base + tid]       = bias[base + tid];
    out[(size_t)b * DD + base + 256 + tid] = bias[base + 256 + tid];

    float p[NBLK];
#pragma unroll
    for (int j = 0; j < NBLK; j++) p[j] = 0.f;

#pragma unroll
    for (int r = 0; r < 2; r++) {
        const int k = base + r * 256 + tid;
        const float xv = x[(size_t)b * DD + k];
        const float4* gr = (const float4*)(gw + (size_t)k * NBLK);
        const float4 w0 = gr[0], w1 = gr[1], w2 = gr[2], w3 = gr[3];
        p[0]  += xv * w0.x;  p[1]  += xv * w0.y;  p[2]  += xv * w0.z;  p[3]  += xv * w0.w;
        p[4]  += xv * w1.x;  p[5]  += xv * w1.y;  p[6]  += xv * w1.z;  p[7]  += xv * w1.w;
        p[8]  += xv * w2.x;  p[9]  += xv * w2.y;  p[10] += xv * w2.z;  p[11] += xv * w2.w;
        p[12] += xv * w3.x;  p[13] += xv * w3.y;  p[14] += xv * w3.z;  p[15] += xv * w3.w;
    }

    // warp butterfly reduce (fixed order -> deterministic)
#pragma unroll
    for (int j = 0; j < NBLK; j++)
#pragma unroll
        for (int off = 16; off > 0; off >>= 1)
            p[j] += __shfl_xor_sync(0xffffffffu, p[j], off);

    __shared__ float ws[8][NBLK];
    if ((tid & 31) == 0) {
#pragma unroll
        for (int j = 0; j < NBLK; j++) ws[tid >> 5][j] = p[j];
    }
    __syncthreads();

    if (tid < NBLK) {
        float s = 0.f;
#pragma unroll
        for (int w = 0; w < 8; w++) s += ws[w][tid];
        g_part[((size_t)b * 4 + ks) * NBLK + tid] = s;
    }
}

// ---------------------------------------------------------------------------
// Kernel 2: finalize gates (sum partials + sigmoid), top-k drop, compaction.
// ---------------------------------------------------------------------------
__global__ __launch_bounds__(512) void compact_kernel(const float* __restrict__ gb)
{
    __shared__ float gm[BATCH * 17];
    const int t = threadIdx.x;

    {
        const int b = t >> 4, j = t & 15;
        const float v = g_part[(b * 4 + 0) * NBLK + j] + g_part[(b * 4 + 1) * NBLK + j]
                      + g_part[(b * 4 + 2) * NBLK + j] + g_part[(b * 4 + 3) * NBLK + j]
                      + gb[j];
        gm[b * 17 + j] = 1.f / (1.f + expf(-v));
    }
    __syncthreads();

    if (t < BATCH) {
        float v[NBLK];
#pragma unroll
        for (int j = 0; j < NBLK; j++) v[j] = gm[t * 17 + j];
        unsigned mask = 0;
        // zero the 8 smallest; strict '<' => lowest index wins ties (matches top_k)
        for (int it = 0; it < NBLK / 2; it++) {
            int best = 0; float bv = 3.4e38f;
            for (int j = 0; j < NBLK; j++)
                if (!((mask >> j) & 1u) && v[j] < bv) { bv = v[j]; best = j; }
            mask |= 1u << best;
        }
#pragma unroll
        for (int j = 0; j < NBLK; j++)
            gm[t * 17 + j] = ((mask >> j) & 1u) ? 0.f : v[j];
    }
    __syncthreads();

    if (t < NBLK) {
        int c = 0;
        for (int b = 0; b < BATCH; b++) {
            const float v = gm[b * 17 + t];
            if (v != 0.f) { g_idx[t * 32 + c] = b; g_gval[t * 32 + c] = v; c++; }
        }
        g_cnt[t] = c;
        for (int s = c; s < 32; s++) { g_idx[t * 32 + s] = 0; g_gval[t * 32 + s] = 0.f; }
    }
}

// ---------------------------------------------------------------------------
// Kernel 3: gated skinny GEMM, f32x2 FFMA with k-parity packed accumulators.
// grid = (64 col-tiles of 32 rows, 4 slot-chunks of 8 compacted batches)
// block = 512: cg = tid>>6 (8 col-groups x 4 rows), kg = tid&63 (64-way K split)
// ---------------------------------------------------------------------------
__device__ __forceinline__ unsigned long long ffma2(
    unsigned long long a, unsigned long long b, unsigned long long c)
{
    unsigned long long d;
    asm("fma.rn.f32x2 %0, %1, %2, %3;" : "=l"(d) : "l"(a), "l"(b), "l"(c));
    return d;
}

__global__ __launch_bounds__(512, 1) void main_kernel(
    const float* __restrict__ x, const float* __restrict__ W,
    const float* __restrict__ bias, float* __restrict__ out)
{
    extern __shared__ float smem[];
    float* xs  = smem;              // 8 rows x 2048 floats = 64 KB
    float* red = smem + 8 * DD;     // 256 x 65 floats

    const int c0  = blockIdx.x * 32;     // first output row of tile
    const int nb  = c0 >> 7;             // gate block
    const int s0  = blockIdx.y * 8;      // first compacted slot
    const int cnt = g_cnt[nb];
    if (s0 >= cnt) return;               // idle chunk -> outputs stay = bias

    const int tid = threadIdx.x;
    const int kg  = tid & 63;            // 0..63 (lanes contiguous in k)
    const int cg  = tid >> 6;            // 0..7

    int bidx[8];
#pragma unroll
    for (int j = 0; j < 8; j++) bidx[j] = g_idx[nb * 32 + s0 + j];  // padded: b=0

    // stage x rows (plain layout, coalesced float4 copies)
    for (int m = tid; m < 4096; m += 512) {
        const int s  = m >> 9;
        const int k4 = m & 511;
        ((float4*)(xs + s * DD))[k4] = ((const float4*)(x + (size_t)bidx[s] * DD))[k4];
    }
    __syncthreads();

    // W rows for this thread's 4 output columns, viewed as k-pair (u64) stream
    const unsigned long long* w64 =
        (const unsigned long long*)(W + (size_t)(c0 + cg * 4) * DD);

    unsigned long long acc[8][4];
#pragma unroll
    for (int s = 0; s < 8; s++)
#pragma unroll
        for (int c = 0; c < 4; c++) acc[s][c] = 0ull;

    unsigned long long wA[4], wB[4];
#pragma unroll
    for (int c = 0; c < 4; c++) wA[c] = w64[c * 1024 + kg];

#pragma unroll 4
    for (int i = 0; i < 16; i++) {
        const int kidx = kg + i * 64;                 // k-pair index (k = 2*kidx)
        const int nidx = (kidx + 64) & 1023;          // next iter (wrap harmless)
#pragma unroll
        for (int c = 0; c < 4; c++) wB[c] = w64[c * 1024 + nidx];   // prefetch

        unsigned long long xv[8];
#pragma unroll
        for (int s = 0; s < 8; s++)
            xv[s] = *(const unsigned long long*)(xs + s * DD + (kidx << 1));

#pragma unroll
        for (int c = 0; c < 4; c++) {
            const unsigned long long wv = wA[c];
#pragma unroll
            for (int s = 0; s < 8; s++)
                acc[s][c] = ffma2(xv[s], wv, acc[s][c]);
        }
#pragma unroll
        for (int c = 0; c < 4; c++) wA[c] = wB[c];
    }

    // horizontal add (even-k + odd-k) and conflict-free partial store:
    // red[(s*32 + cg*4 + c)*65 + kg] -> banks (idx + kg) % 32, all distinct
#pragma unroll
    for (int s = 0; s < 8; s++) {
#pragma unroll
        for (int c = 0; c < 4; c++) {
            const unsigned long long v = acc[s][c];
            const float lo = __uint_as_float((unsigned)(v & 0xffffffffu));
            const float hi = __uint_as_float((unsigned)(v >> 32));
            red[(s * 32 + cg * 4 + c) * 65 + kg] = lo + hi;
        }
    }
    __syncthreads();

    if (tid < 256) {
        const int s  = tid >> 5;
        const int cp = tid & 31;
        const float* r = red + tid * 65;   // idx = s*32+cp = tid
        // 4-way split sum over 64 kg partials (fixed order -> deterministic)
        float s0a = 0.f, s1a = 0.f, s2a = 0.f, s3a = 0.f;
#pragma unroll
        for (int k = 0; k < 64; k += 4) {
            s0a += r[k]; s1a += r[k + 1]; s2a += r[k + 2]; s3a += r[k + 3];
        }
        const float sum = (s0a + s1a) + (s2a + s3a);
        if (s0 + s < cnt) {
            const float g = g_gval[nb * 32 + s0 + s];
            out[(size_t)bidx[s] * DD + c0 + cp] = g * sum + bias[c0 + cp];
        }
    }
}

// ---------------------------------------------------------------------------
extern "C" void kernel_launch(void* const* d_in, const int* in_sizes, int n_in,
                              void* d_out, int out_size)
{
    (void)in_sizes; (void)n_in; (void)out_size;
    const float* x    = (const float*)d_in[0];
    const float* gw   = (const float*)d_in[1];
    const float* gb   = (const float*)d_in[2];
    const float* W    = (const float*)d_in[3];
    const float* bias = (const float*)d_in[4];
    float* out = (float*)d_out;

    static int smem_set = 0;
    if (!smem_set) {
        cudaFuncSetAttribute(main_kernel,
                             cudaFuncAttributeMaxDynamicSharedMemorySize,
                             (8 * DD + 256 * 65) * 4);
        smem_set = 1;
    }

    gate_kernel<<<dim3(32, 4), 256>>>(x, gw, bias, out);
    compact_kernel<<<1, 512>>>(gb);
    main_kernel<<<dim3(64, 4), 512, (8 * DD + 256 * 65) * 4>>>(x, W, bias, out);
}

// round 9
// speedup vs baseline: 2.4489x; 1.0399x over previous
#include <cuda_runtime.h>
#include <cstdint>

#define DD    2048
#define NBLK  16
#define BATCH 32

// Scratch (no allocations allowed -> __device__ global; rewritten every launch)
__device__ float g_gates[BATCH * NBLK];   // final gates (0 for dropped)

// ---------------------------------------------------------------------------
// Kernel 1: full gate network per batch. One CTA (512 thr) per batch sample.
// Computes logits, sigmoid, drops 8 smallest, writes final gates.
// Also fills out with bias (inactive (b,i) outputs are exactly bias[i]).
// ---------------------------------------------------------------------------
__global__ __launch_bounds__(512) void gate_kernel(
    const float* __restrict__ x, const float* __restrict__ gw,
    const float* __restrict__ gb, const float* __restrict__ bias,
    float* __restrict__ out)
{
    const int b   = blockIdx.x;
    const int tid = threadIdx.x;

    // bias fill for this batch row (coalesced float4)
    ((float4*)(out + (size_t)b * DD))[tid] = ((const float4*)bias)[tid];

    float p[NBLK];
#pragma unroll
    for (int j = 0; j < NBLK; j++) p[j] = 0.f;

#pragma unroll
    for (int r = 0; r < 4; r++) {
        const int k = r * 512 + tid;
        const float xv = x[(size_t)b * DD + k];
        const float4* gr = (const float4*)(gw + (size_t)k * NBLK);
        const float4 w0 = gr[0], w1 = gr[1], w2 = gr[2], w3 = gr[3];
        p[0]  += xv * w0.x;  p[1]  += xv * w0.y;  p[2]  += xv * w0.z;  p[3]  += xv * w0.w;
        p[4]  += xv * w1.x;  p[5]  += xv * w1.y;  p[6]  += xv * w1.z;  p[7]  += xv * w1.w;
        p[8]  += xv * w2.x;  p[9]  += xv * w2.y;  p[10] += xv * w2.z;  p[11] += xv * w2.w;
        p[12] += xv * w3.x;  p[13] += xv * w3.y;  p[14] += xv * w3.z;  p[15] += xv * w3.w;
    }

    // warp butterfly reduce (fixed order -> deterministic)
#pragma unroll
    for (int j = 0; j < NBLK; j++)
#pragma unroll
        for (int off = 16; off > 0; off >>= 1)
            p[j] += __shfl_xor_sync(0xffffffffu, p[j], off);

    __shared__ float ws[16][NBLK + 1];
    if ((tid & 31) == 0) {
#pragma unroll
        for (int j = 0; j < NBLK; j++) ws[tid >> 5][j] = p[j];
    }
    __syncthreads();

    __shared__ float gv[NBLK];
    if (tid < NBLK) {
        float s = 0.f;
#pragma unroll
        for (int w = 0; w < 16; w++) s += ws[w][tid];
        gv[tid] = 1.f / (1.f + expf(-(s + gb[tid])));
    }
    __syncthreads();

    if (tid == 0) {
        float v[NBLK];
#pragma unroll
        for (int j = 0; j < NBLK; j++) v[j] = gv[j];
        unsigned mask = 0;
        // drop the 8 smallest; strict '<' => lowest index wins ties (matches top_k)
        for (int it = 0; it < NBLK / 2; it++) {
            int best = 0; float bv = 3.4e38f;
            for (int j = 0; j < NBLK; j++)
                if (!((mask >> j) & 1u) && v[j] < bv) { bv = v[j]; best = j; }
            mask |= 1u << best;
        }
#pragma unroll
        for (int j = 0; j < NBLK; j++)
            g_gates[b * NBLK + j] = ((mask >> j) & 1u) ? 0.f : v[j];
    }
}

// ---------------------------------------------------------------------------
// Kernel 2: gated skinny GEMM, f32x2 FFMA, inline ballot compaction.
// grid = (64 col-tiles of 32 rows, 4 slot-chunks of 8 compacted batches)
// block = 512: cg = tid>>6 (8 col-groups x 4 rows), kg = tid&63 (64-way K split)
// ---------------------------------------------------------------------------
__device__ __forceinline__ unsigned long long ffma2(
    unsigned long long a, unsigned long long b, unsigned long long c)
{
    unsigned long long d;
    asm("fma.rn.f32x2 %0, %1, %2, %3;" : "=l"(d) : "l"(a), "l"(b), "l"(c));
    return d;
}

__global__ __launch_bounds__(512, 1) void main_kernel(
    const float* __restrict__ x, const float* __restrict__ W,
    const float* __restrict__ bias, float* __restrict__ out)
{
    extern __shared__ float smem[];
    float* xs  = smem;              // 8 rows x 2048 floats = 64 KB
    float* red = smem + 8 * DD;     // 256 x 65 floats

    __shared__ int   s_bidx[8];
    __shared__ float s_gvl[8];
    __shared__ int   s_cnt;

    const int c0  = blockIdx.x * 32;     // first output row of tile
    const int nb  = c0 >> 7;             // gate block
    const int s0  = blockIdx.y * 8;      // first compacted slot
    const int tid = threadIdx.x;

    // inline compaction of active batches for this gate block (warp 0)
    if (tid < 32) {
        if (tid < 8) { s_bidx[tid] = 0; s_gvl[tid] = 0.f; }   // pad defaults
        __syncwarp();
        const float v = g_gates[tid * NBLK + nb];
        const unsigned m = __ballot_sync(0xffffffffu, v != 0.f);
        if (tid == 0) s_cnt = __popc(m);
        const int slot = __popc(m & ((1u << tid) - 1u)) - s0;
        if (v != 0.f && slot >= 0 && slot < 8) { s_bidx[slot] = tid; s_gvl[slot] = v; }
    }
    __syncthreads();

    const int cnt = s_cnt;
    if (s0 >= cnt) return;               // idle chunk -> outputs stay = bias

    int bidx[8];
#pragma unroll
    for (int j = 0; j < 8; j++) bidx[j] = s_bidx[j];

    // stage x rows (plain layout, coalesced float4 copies)
    for (int m = tid; m < 4096; m += 512) {
        const int s  = m >> 9;
        const int k4 = m & 511;
        ((float4*)(xs + s * DD))[k4] = ((const float4*)(x + (size_t)bidx[s] * DD))[k4];
    }
    __syncthreads();

    const int kg = tid & 63;             // 0..63 (lanes contiguous in k)
    const int cg = tid >> 6;             // 0..7

    // W rows for this thread's 4 output columns, viewed as k-pair (u64) stream
    const unsigned long long* w64 =
        (const unsigned long long*)(W + (size_t)(c0 + cg * 4) * DD);

    unsigned long long acc[8][4];
#pragma unroll
    for (int s = 0; s < 8; s++)
#pragma unroll
        for (int c = 0; c < 4; c++) acc[s][c] = 0ull;

    unsigned long long wA[4], wB[4];
#pragma unroll
    for (int c = 0; c < 4; c++) wA[c] = w64[c * 1024 + kg];

#pragma unroll 4
    for (int i = 0; i < 16; i++) {
        const int kidx = kg + i * 64;                 // k-pair index (k = 2*kidx)
        const int nidx = (kidx + 64) & 1023;          // next iter (wrap harmless)
#pragma unroll
        for (int c = 0; c < 4; c++) wB[c] = w64[c * 1024 + nidx];   // prefetch

        unsigned long long xv[8];
#pragma unroll
        for (int s = 0; s < 8; s++)
            xv[s] = *(const unsigned long long*)(xs + s * DD + (kidx << 1));

#pragma unroll
        for (int c = 0; c < 4; c++) {
            const unsigned long long wv = wA[c];
#pragma unroll
            for (int s = 0; s < 8; s++)
                acc[s][c] = ffma2(xv[s], wv, acc[s][c]);
        }
#pragma unroll
        for (int c = 0; c < 4; c++) wA[c] = wB[c];
    }

    // horizontal add (even-k + odd-k) and conflict-free partial store:
    // red[(s*32 + cg*4 + c)*65 + kg] -> banks (idx + kg) % 32, all distinct
#pragma unroll
    for (int s = 0; s < 8; s++) {
#pragma unroll
        for (int c = 0; c < 4; c++) {
            const unsigned long long v = acc[s][c];
            const float lo = __uint_as_float((unsigned)(v & 0xffffffffu));
            const float hi = __uint_as_float((unsigned)(v >> 32));
            red[(s * 32 + cg * 4 + c) * 65 + kg] = lo + hi;
        }
    }
    __syncthreads();

    if (tid < 256) {
        const int s  = tid >> 5;
        const int cp = tid & 31;
        const float* r = red + tid * 65;   // idx = s*32+cp = tid
        float a0 = 0.f, a1 = 0.f, a2 = 0.f, a3 = 0.f;
#pragma unroll
        for (int k = 0; k < 64; k += 4) {
            a0 += r[k]; a1 += r[k + 1]; a2 += r[k + 2]; a3 += r[k + 3];
        }
        const float sum = (a0 + a1) + (a2 + a3);
        if (s0 + s < cnt)
            out[(size_t)s_bidx[s] * DD + c0 + cp] = s_gvl[s] * sum + bias[c0 + cp];
    }
}

// ---------------------------------------------------------------------------
extern "C" void kernel_launch(void* const* d_in, const int* in_sizes, int n_in,
                              void* d_out, int out_size)
{
    (void)in_sizes; (void)n_in; (void)out_size;
    const float* x    = (const float*)d_in[0];
    const float* gw   = (const float*)d_in[1];
    const float* gb   = (const float*)d_in[2];
    const float* W    = (const float*)d_in[3];
    const float* bias = (const float*)d_in[4];
    float* out = (float*)d_out;

    static int smem_set = 0;
    if (!smem_set) {
        cudaFuncSetAttribute(main_kernel,
                             cudaFuncAttributeMaxDynamicSharedMemorySize,
                             (8 * DD + 256 * 65) * 4);
        smem_set = 1;
    }

    gate_kernel<<<32, 512>>>(x, gw, gb, bias, out);
    main_kernel<<<dim3(64, 4), 512, (8 * DD + 256 * 65) * 4>>>(x, W, bias, out);
}